// round 10
// baseline (speedup 1.0000x reference)
#include <cuda_runtime.h>
#include <cuda_bf16.h>

// Problem constants (fixed shapes per reference)
#define CC 9
#define HH 180
#define WW 240
#define BB 8
#define NN 100000
#define HW (HH * WW)                   // 43200
#define NUM_VOXELS (2 * CC * HW * BB)  // 6220800
#define NCELLS (BB * 2 * HW)           // 691200 (pixel x polarity x batch)
#define CPAD 12                        // bins padded 9 -> 12 (16B alignment)

// Piecewise-linear table of the scalar MLP f(s), s in [-1, 1].
// LeakyReLU net on scalar input is piecewise-linear; lerp error is linear in
// cell width (measured: 1.08e-6 @8192, 3.2e-6 @4096, 2.7e-5 @1024).
#define TM 1024

#define JP 104                          // w2 row stride in smem (16B-aligned quads)

__device__ float g_table[TM];
// Zero at module load; re-zeroed at the START of every launch by the zero
// blocks of build_and_zero_kernel (before scatter runs, by stream order).
__device__ float g_scratch[(size_t)NCELLS * CPAD];   // 33.2 MB

__device__ __forceinline__ float lrelu(float v) {
    return fmaxf(v, 0.1f * v);    // leaky_relu slope 0.1
}

// ---------------------------------------------------------------------------
// Fused build + scratch-zero kernel.
// Blocks [0, TBLK): table build — ONE WARP PER SAMPLE, w2 staged in shared.
//   Lane l owns hidden cols 4l..4l+3 (lanes 25-31 predicated off). Per i:
//   broadcast LDS.64 of {b1,w1}, one LDS.128 of the w2 quad, 4 FMA.
// Blocks [TBLK, TBLK+ZBLK): grid-stride zero of g_scratch. This runs on the
//   7/8 of the chip the latency-bound build leaves idle (build: occ 12%,
//   issue 14%, mem ~0%), so the 33MB reset is hidden under the build shadow
//   and transpose no longer pays for it.
// ---------------------------------------------------------------------------
#define BT_THREADS 256
#define BT_WPB (BT_THREADS / 32)                 // 8 samples per block
#define TBLK (TM / BT_WPB)                       // 128 table blocks
#define ZBLK 896                                 // zeroing blocks
#define SCRATCH_F4 ((NCELLS * CPAD) / 4)         // 2,073,600 float4s

__global__ __launch_bounds__(BT_THREADS) void build_and_zero_kernel(
    const float* __restrict__ w1, const float* __restrict__ b1,
    const float* __restrict__ w2, const float* __restrict__ b2,
    const float* __restrict__ w3, const float* __restrict__ b3)
{
    int tid = threadIdx.x;

    if (blockIdx.x >= TBLK) {
        // ---- scratch zero path ----
        float4* s4 = reinterpret_cast<float4*>(g_scratch);
        float4 z = make_float4(0.f, 0.f, 0.f, 0.f);
        int i = (blockIdx.x - TBLK) * BT_THREADS + tid;
        int stride = ZBLK * BT_THREADS;
        for (; i < SCRATCH_F4; i += stride)
            s4[i] = z;
        return;
    }

    // ---- table build path ----
    __shared__ float  sw2[100 * JP];             // [i][j], quad-aligned rows
    __shared__ float2 s_bw1[100];                // {b1[i], w1[i]}

    int lane = tid & 31;
    int wid  = tid >> 5;

    // stage w2 as float4s (global rows are 400B, 16B-aligned)
    for (int f = tid; f < 2500; f += BT_THREADS) {
        float4 v = reinterpret_cast<const float4*>(w2)[f];
        int r = f / 25, c = f - r * 25;
        *reinterpret_cast<float4*>(&sw2[r * JP + c * 4]) = v;
    }
    if (tid < 100) s_bw1[tid] = make_float2(b1[tid], w1[tid]);
    __syncthreads();

    int k = blockIdx.x * BT_WPB + wid;           // sample index, < TM
    float s = -1.0f + 2.0f * (float)k / (float)(TM - 1);

    int j0 = lane * 4;
    bool active = (lane < 25);

    float a0 = 0.f, a1 = 0.f, a2 = 0.f, a3 = 0.f;
    if (active) {
        float4 bb = *reinterpret_cast<const float4*>(b2 + j0);
        a0 = bb.x; a1 = bb.y; a2 = bb.z; a3 = bb.w;
    }

#pragma unroll 4
    for (int i = 0; i < 100; i++) {
        float2 bw = s_bw1[i];                    // broadcast
        float h = lrelu(fmaf(s, bw.y, bw.x));
        if (active) {
            float4 w = *reinterpret_cast<const float4*>(&sw2[i * JP + j0]);
            a0 = fmaf(h, w.x, a0);
            a1 = fmaf(h, w.y, a1);
            a2 = fmaf(h, w.z, a2);
            a3 = fmaf(h, w.w, a3);
        }
    }

    float part = 0.f;
    if (active) {
        float4 w3v = *reinterpret_cast<const float4*>(w3 + j0);
        part = lrelu(a0) * w3v.x + lrelu(a1) * w3v.y
             + lrelu(a2) * w3v.z + lrelu(a3) * w3v.w;
    }

    part += __shfl_xor_sync(0xffffffffu, part, 16);
    part += __shfl_xor_sync(0xffffffffu, part, 8);
    part += __shfl_xor_sync(0xffffffffu, part, 4);
    part += __shfl_xor_sync(0xffffffffu, part, 2);
    part += __shfl_xor_sync(0xffffffffu, part, 1);

    if (lane == 0)
        g_table[k] = part + b3[0];
}

// ---------------------------------------------------------------------------
// Scatter: one thread per event. 9 bin-values via table lerp, accumulated
// into bin-CONTIGUOUS scratch with 2x red.v4 + 1 scalar RED (3 lanes/event,
// one 128B line). cell = x + W*y + HW*(p + 2*b).
// ---------------------------------------------------------------------------
__global__ __launch_bounds__(256) void scatter_kernel(
    const float* __restrict__ t, const int* __restrict__ x,
    const int* __restrict__ y, const int* __restrict__ p,
    int total)
{
    int e = blockIdx.x * blockDim.x + threadIdx.x;
    if (e >= total) return;

    float tf = t[e];
    int b = e / NN;
    int cell = x[e] + WW * y[e] + HW * (p[e] + 2 * b);
    float* dst = g_scratch + (size_t)cell * CPAD;

    const float scale = (float)(TM - 1) * 0.5f;

    float v[9];
#pragma unroll
    for (int i = 0; i < CC; i++) {
        float s = tf - (float)i * 0.125f;     // i/(C-1), C-1 = 8
        float fi = (s + 1.0f) * scale;
        int i0 = (int)fi;
        i0 = max(0, min(i0, TM - 2));
        float fr = fi - (float)i0;
        float f0 = g_table[i0];
        float f1 = g_table[i0 + 1];
        v[i] = tf * fmaf(f1 - f0, fr, f0);
    }

    asm volatile("red.global.add.v4.f32 [%0], {%1,%2,%3,%4};"
                 :: "l"(dst), "f"(v[0]), "f"(v[1]), "f"(v[2]), "f"(v[3])
                 : "memory");
    asm volatile("red.global.add.v4.f32 [%0], {%1,%2,%3,%4};"
                 :: "l"(dst + 4), "f"(v[4]), "f"(v[5]), "f"(v[6]), "f"(v[7])
                 : "memory");
    atomicAdd(dst + 8, v[8]);
}

// ---------------------------------------------------------------------------
// Transpose: scratch[cell][c] -> out[(q*C + c)*HW + pix], q = cell/HW.
// q = p + 2b, so (q*C + c)*HW + pix is exactly the reference's flat voxel
// index / concatenated output layout. Writes EVERY output element (no d_out
// zeroing needed). Scratch reset now happens in build_and_zero_kernel.
// ---------------------------------------------------------------------------
__global__ __launch_bounds__(256) void transpose_kernel(float* __restrict__ out)
{
    int cell = blockIdx.x * blockDim.x + threadIdx.x;   // < NCELLS exactly
    const float4* src = reinterpret_cast<const float4*>(g_scratch + (size_t)cell * CPAD);
    float4 a  = src[0];
    float4 c4 = src[1];
    float c8  = g_scratch[(size_t)cell * CPAD + 8];

    int q   = cell / HW;
    int pix = cell - q * HW;
    float* o = out + (size_t)q * CC * HW + pix;

    o[0 * HW] = a.x;  o[1 * HW] = a.y;  o[2 * HW] = a.z;  o[3 * HW] = a.w;
    o[4 * HW] = c4.x; o[5 * HW] = c4.y; o[6 * HW] = c4.z; o[7 * HW] = c4.w;
    o[8 * HW] = c8;
}

// ---------------------------------------------------------------------------
// Launch.  metadata order: t, w1, b1, w2, b2, w3, b3, x, y, p
// ---------------------------------------------------------------------------
extern "C" void kernel_launch(void* const* d_in, const int* in_sizes, int n_in,
                              void* d_out, int out_size)
{
    const float* t  = (const float*)d_in[0];
    const float* w1 = (const float*)d_in[1];
    const float* b1 = (const float*)d_in[2];
    const float* w2 = (const float*)d_in[3];
    const float* b2 = (const float*)d_in[4];
    const float* w3 = (const float*)d_in[5];
    const float* b3 = (const float*)d_in[6];
    const int*   x  = (const int*)d_in[7];
    const int*   y  = (const int*)d_in[8];
    const int*   p  = (const int*)d_in[9];
    float* out = (float*)d_out;

    int total = in_sizes[0];          // B*N = 800000

    build_and_zero_kernel<<<TBLK + ZBLK, BT_THREADS>>>(w1, b1, w2, b2, w3, b3);
    scatter_kernel<<<(total + 255) / 256, 256>>>(t, x, y, p, total);
    transpose_kernel<<<NCELLS / 256, 256>>>(out);
}